// round 15
// baseline (speedup 1.0000x reference)
#include <cuda_runtime.h>
#include <math.h>
#include <stdint.h>

#define BATCH 2
#define SEQ   2048
#define DMODEL 2048
#define NHEAD 16
#define DHEAD 128
#define D3    (3*DMODEL)
#define KDIM  2048

// Scratch (device globals — no allocation allowed)
__device__ float g_qkv[(size_t)BATCH * SEQ * D3];        // [B,S,3D] raw GEMM out
__device__ float g_attn[(size_t)BATCH * SEQ * DMODEL];   // [B,S,D]
__device__ float g_cos[SEQ * 64];
__device__ float g_sin[SEQ * 64];

__device__ __forceinline__ uint32_t f2tf32(float x) {
    uint32_t r;
    asm("cvt.rna.tf32.f32 %0, %1;" : "=r"(r) : "f"(x));
    return r;
}
__device__ __forceinline__ float tf32r(float x) {
    float r;
    asm("cvt.rna.tf32.f32 %0, %1;" : "=f"(r) : "f"(x));
    return r;
}

__device__ __forceinline__ void mma_tf32(float& d0, float& d1, float& d2, float& d3,
                                         uint32_t a0, uint32_t a1, uint32_t a2, uint32_t a3,
                                         uint32_t b0, uint32_t b1) {
    asm volatile(
        "mma.sync.aligned.m16n8k8.row.col.f32.tf32.tf32.f32 "
        "{%0,%1,%2,%3}, {%4,%5,%6,%7}, {%8,%9}, {%0,%1,%2,%3};"
        : "+f"(d0), "+f"(d1), "+f"(d2), "+f"(d3)
        : "r"(a0), "r"(a1), "r"(a2), "r"(a3), "r"(b0), "r"(b1));
}

// ===========================================================================
// mma.sync tf32 GEMM, BK=64, 256 threads (round-11 exact — best measured).
// CTA tile 128x128, 8 warps (4m x 2n), warp 32x64.
//   A smem [128][AS2=68], B smem [64][BS2=136] (conflict-free frag reads)
// ===========================================================================
#define BK2 64
#define NT2 (KDIM / BK2)          // 32
#define AS2 68
#define BS2 136
#define A_STG2 (128 * AS2)        // 8704 floats
#define B_STG2 (64 * BS2)         // 8704 floats
#define STG2 (A_STG2 + B_STG2)    // 17408 floats
#define GEMM_SMEM (2 * STG2 * 4)  // 139264 B

__global__ void __launch_bounds__(256, 1)
mma_gemm_kernel(const float* __restrict__ A, const float* __restrict__ W,
                const float* __restrict__ bias, float* __restrict__ C, int N) {
    extern __shared__ float smem[];

    const int tid  = threadIdx.x;
    const int lane = tid & 31;
    const int warp = tid >> 5;
    const int wm   = warp >> 1;
    const int wn   = warp & 1;
    const int grp  = lane >> 2;
    const int tig  = lane & 3;
    const int brow = blockIdx.y;
    const int bcol = blockIdx.x;

    const int arow  = tid >> 4;   // + i*16
    const int acol4 = tid & 15;
    const int bkrow = tid >> 5;   // + i*8
    const int bcol4 = tid & 31;

    const float* Ag = A + (size_t)(brow * 128 + arow) * KDIM + acol4 * 4;
    const float* Wg = W + (size_t)bkrow * N + bcol * 128 + bcol4 * 4;

    float4 bufA[4], bufB[4];

    auto ldg_half = [&](int j, int h) {
        int k0 = j * BK2;
#pragma unroll
        for (int t = 0; t < 4; t++) {
            int i = h * 4 + t;
            bufA[t] = *(const float4*)(Ag + (size_t)(i * 16) * KDIM + k0);
            bufB[t] = *(const float4*)(Wg + (size_t)(k0 + i * 8) * N);
        }
    };

    auto sts_half = [&](int s, int h) {
        float* sa = smem + s * STG2;
        float* sb = sa + A_STG2;
#pragma unroll
        for (int t = 0; t < 4; t++) {
            int i = h * 4 + t;
            uint4 va;
            va.x = f2tf32(bufA[t].x); va.y = f2tf32(bufA[t].y);
            va.z = f2tf32(bufA[t].z); va.w = f2tf32(bufA[t].w);
            *(uint4*)(sa + (arow + i * 16) * AS2 + acol4 * 4) = va;
            uint4 vb;
            vb.x = f2tf32(bufB[t].x); vb.y = f2tf32(bufB[t].y);
            vb.z = f2tf32(bufB[t].z); vb.w = f2tf32(bufB[t].w);
            *(uint4*)(sb + (bkrow + i * 8) * BS2 + bcol4 * 4) = vb;
        }
    };

    float acc[2][8][4];
#pragma unroll
    for (int m = 0; m < 2; m++)
#pragma unroll
        for (int n = 0; n < 8; n++)
#pragma unroll
            for (int c = 0; c < 4; c++) acc[m][n][c] = 0.f;

    const int rb0 = wm * 32 + grp;
    const int cb0 = wn * 64 + grp;

    auto compute_half = [&](int s, int h) {
        const float* sa = smem + s * STG2;
        const float* sb = sa + A_STG2;
#pragma unroll
        for (int ks = 0; ks < 4; ks++) {
            int kc = (h * 4 + ks) * 8 + tig;
            uint32_t af[2][4];
#pragma unroll
            for (int m = 0; m < 2; m++) {
                const float* ap = sa + (rb0 + m * 16) * AS2 + kc;
                af[m][0] = __float_as_uint(ap[0]);
                af[m][1] = __float_as_uint(ap[8 * AS2]);
                af[m][2] = __float_as_uint(ap[4]);
                af[m][3] = __float_as_uint(ap[8 * AS2 + 4]);
            }
            uint32_t bf[8][2];
            const float* bp = sb + kc * BS2 + cb0;
#pragma unroll
            for (int n = 0; n < 8; n++) {
                bf[n][0] = __float_as_uint(bp[n * 8]);
                bf[n][1] = __float_as_uint(bp[4 * BS2 + n * 8]);
            }
#pragma unroll
            for (int m = 0; m < 2; m++)
#pragma unroll
                for (int n = 0; n < 8; n++)
                    mma_tf32(acc[m][n][0], acc[m][n][1], acc[m][n][2], acc[m][n][3],
                             af[m][0], af[m][1], af[m][2], af[m][3],
                             bf[n][0], bf[n][1]);
        }
    };

    ldg_half(0, 0); sts_half(0, 0);
    ldg_half(0, 1); sts_half(0, 1);
    __syncthreads();

    for (int j = 0; j < NT2; j++) {
        const int cur = j & 1;
        const int nxt = cur ^ 1;
        const bool pre = (j + 1 < NT2);

        if (pre) ldg_half(j + 1, 0);
        compute_half(cur, 0);
        if (pre) { sts_half(nxt, 0); ldg_half(j + 1, 1); }
        compute_half(cur, 1);
        if (pre) sts_half(nxt, 1);
        __syncthreads();
    }

#pragma unroll
    for (int m = 0; m < 2; m++) {
        int row0 = brow * 128 + wm * 32 + m * 16 + grp;
#pragma unroll
        for (int n = 0; n < 8; n++) {
            int col = bcol * 128 + wn * 64 + n * 8 + tig * 2;
            float2 bv = *(const float2*)(bias + col);
            float2 o0, o1;
            o0.x = acc[m][n][0] + bv.x; o0.y = acc[m][n][1] + bv.y;
            o1.x = acc[m][n][2] + bv.x; o1.y = acc[m][n][3] + bv.y;
            *(float2*)(C + (size_t)row0 * N + col)       = o0;
            *(float2*)(C + (size_t)(row0 + 8) * N + col) = o1;
        }
    }
}

// ===========================================================================
// RoPE table (cos/sin only; application fused into attention loads)
// ===========================================================================
__global__ void rope_table_kernel() {
    int idx = blockIdx.x * blockDim.x + threadIdx.x;
    if (idx >= SEQ * 64) return;
    int s = idx >> 6;
    int i = idx & 63;
    double theta = exp(-(double)i * log(10000.0) / 64.0);
    float tf = (float)theta;
    float ang = (float)s * tf;
    float sv, cv;
    sincosf(ang, &sv, &cv);
    g_cos[idx] = cv;
    g_sin[idx] = sv;
}

// ===========================================================================
// Flash attention (round-14 exact — verified correct, ~350us).
// CTA: 128 q-rows (8 warps x 16 rows), kv-tile 64 keys. RoPE fused.
// Causal fast path iff warp's MIN row fully unmasked; jmax clamped to 8.
// ===========================================================================
#define ATQ_PAD 132
#define ATK_PAD 132
#define ATV_PAD 136
#define ATP_PAD 68
#define ATQ_OFF 0
#define ATK_OFF (128 * ATQ_PAD)
#define ATV_OFF (ATK_OFF + 64 * ATK_PAD)
#define ATP_OFF (ATV_OFF + 64 * ATV_PAD)
#define ATT_SMEM_FLOATS (ATP_OFF + 8 * 16 * ATP_PAD)

__global__ void __launch_bounds__(256, 1)
attn_mma_kernel(const float* __restrict__ qkv, float* __restrict__ out) {
    extern __shared__ float sm[];
    float* Qs = sm + ATQ_OFF;
    float* Ks = sm + ATK_OFF;
    float* Vs = sm + ATV_OFF;

    const float SCALE = 0.08838834764831845f;  // 1/sqrt(128)
    const float NEG_BIG = -3.0e38f;

    const int qt = (int)gridDim.x - 1 - (int)blockIdx.x;
    const int h = blockIdx.y, b = blockIdx.z;
    const int tid = threadIdx.x;
    const int lane = tid & 31, warp = tid >> 5;
    const int grp = lane >> 2, tig = lane & 3;

    float* Pw = sm + ATP_OFF + warp * (16 * ATP_PAD);

    const float* qbase = qkv + (size_t)(b * SEQ) * D3 + h * DHEAD;
    const float* kbase = qbase + DMODEL;
    const float* vbase = qbase + 2 * DMODEL;

    const int qrow0 = qt * 128;
    const int r_lo = warp * 16 + grp;
    const int r_hi = r_lo + 8;

    // ---- Load Q with fused RoPE + scale + tf32 round ----
#pragma unroll
    for (int t = 0; t < 8; t++) {
        int lin = tid + t * 256;
        int row = lin >> 4;
        int d0 = (lin & 15) * 4;
        int s = qrow0 + row;
        const float* qp = qbase + (size_t)s * D3;
        float4 q0 = *(const float4*)(qp + d0);
        float4 q1 = *(const float4*)(qp + d0 + 64);
        float4 cv = *(const float4*)(g_cos + s * 64 + d0);
        float4 sv = *(const float4*)(g_sin + s * 64 + d0);
        float4 o0, o1;
        o0.x = tf32r(SCALE * (cv.x * q0.x - sv.x * q1.x));
        o0.y = tf32r(SCALE * (cv.y * q0.y - sv.y * q1.y));
        o0.z = tf32r(SCALE * (cv.z * q0.z - sv.z * q1.z));
        o0.w = tf32r(SCALE * (cv.w * q0.w - sv.w * q1.w));
        o1.x = tf32r(SCALE * (cv.x * q1.x + sv.x * q0.x));
        o1.y = tf32r(SCALE * (cv.y * q1.y + sv.y * q0.y));
        o1.z = tf32r(SCALE * (cv.z * q1.z + sv.z * q0.z));
        o1.w = tf32r(SCALE * (cv.w * q1.w + sv.w * q0.w));
        *(float4*)(Qs + row * ATQ_PAD + d0)      = o0;
        *(float4*)(Qs + row * ATQ_PAD + d0 + 64) = o1;
    }

    float oacc[16][4];
#pragma unroll
    for (int j = 0; j < 16; j++)
#pragma unroll
        for (int c = 0; c < 4; c++) oacc[j][c] = 0.f;

    float m_lo = NEG_BIG, m_hi = NEG_BIG;
    float l_lo = 0.f, l_hi = 0.f;

    const int nkt = 2 * qt + 2;

    for (int kt = 0; kt < nkt; kt++) {
        const int key0 = kt * 64;
        const int doff = qrow0 - key0;

        __syncthreads();

        // ---- Load K with fused RoPE + tf32 round ----
#pragma unroll
        for (int t = 0; t < 4; t++) {
            int lin = tid + t * 256;
            int row = lin >> 4;
            int d0 = (lin & 15) * 4;
            int s = key0 + row;
            const float* kp = kbase + (size_t)s * D3;
            float4 k0 = *(const float4*)(kp + d0);
            float4 k1 = *(const float4*)(kp + d0 + 64);
            float4 cv = *(const float4*)(g_cos + s * 64 + d0);
            float4 sv = *(const float4*)(g_sin + s * 64 + d0);
            float4 o0, o1;
            o0.x = tf32r(cv.x * k0.x - sv.x * k1.x);
            o0.y = tf32r(cv.y * k0.y - sv.y * k1.y);
            o0.z = tf32r(cv.z * k0.z - sv.z * k1.z);
            o0.w = tf32r(cv.w * k0.w - sv.w * k1.w);
            o1.x = tf32r(cv.x * k1.x + sv.x * k0.x);
            o1.y = tf32r(cv.y * k1.y + sv.y * k0.y);
            o1.z = tf32r(cv.z * k1.z + sv.z * k0.z);
            o1.w = tf32r(cv.w * k1.w + sv.w * k0.w);
            *(float4*)(Ks + row * ATK_PAD + d0)      = o0;
            *(float4*)(Ks + row * ATK_PAD + d0 + 64) = o1;
        }
        // ---- Load V with tf32 round ----
#pragma unroll
        for (int t = 0; t < 8; t++) {
            int lin = tid + t * 256;
            int row = lin >> 5;
            int d0 = (lin & 31) * 4;
            float4 vv = *(const float4*)(vbase + (size_t)(key0 + row) * D3 + d0);
            float4 vo;
            vo.x = tf32r(vv.x); vo.y = tf32r(vv.y);
            vo.z = tf32r(vv.z); vo.w = tf32r(vv.w);
            *(float4*)(Vs + row * ATV_PAD + d0) = vo;
        }
        __syncthreads();

        const float* qpA = Qs + r_lo * ATQ_PAD;
        const float* kpB = Ks + grp * ATK_PAD;

        const int limit_min = warp * 16 + doff;
        const int limit_max = limit_min + 15;

        float al_lo, al_hi;
        int ksmax;

        if (limit_min >= 63) {
            // ======== FULL TILE ========
            ksmax = 8;
            float sacc[8][4];
#pragma unroll
            for (int j = 0; j < 8; j++)
#pragma unroll
                for (int c = 0; c < 4; c++) sacc[j][c] = 0.f;

#pragma unroll 4
            for (int ks = 0; ks < 16; ks++) {
                int kc = ks * 8 + tig;
                uint32_t a0 = __float_as_uint(qpA[kc]);
                uint32_t a1 = __float_as_uint(qpA[8 * ATQ_PAD + kc]);
                uint32_t a2 = __float_as_uint(qpA[kc + 4]);
                uint32_t a3 = __float_as_uint(qpA[8 * ATQ_PAD + kc + 4]);
#pragma unroll
                for (int j = 0; j < 8; j++) {
                    uint32_t b0 = __float_as_uint(kpB[j * 8 * ATK_PAD + kc]);
                    uint32_t b1 = __float_as_uint(kpB[j * 8 * ATK_PAD + kc + 4]);
                    mma_tf32(sacc[j][0], sacc[j][1], sacc[j][2], sacc[j][3],
                             a0, a1, a2, a3, b0, b1);
                }
            }

            float pmax_lo = NEG_BIG, pmax_hi = NEG_BIG;
#pragma unroll
            for (int j = 0; j < 8; j++) {
                pmax_lo = fmaxf(pmax_lo, fmaxf(sacc[j][0], sacc[j][1]));
                pmax_hi = fmaxf(pmax_hi, fmaxf(sacc[j][2], sacc[j][3]));
            }
            pmax_lo = fmaxf(pmax_lo, __shfl_xor_sync(0xFFFFFFFF, pmax_lo, 1));
            pmax_lo = fmaxf(pmax_lo, __shfl_xor_sync(0xFFFFFFFF, pmax_lo, 2));
            pmax_hi = fmaxf(pmax_hi, __shfl_xor_sync(0xFFFFFFFF, pmax_hi, 1));
            pmax_hi = fmaxf(pmax_hi, __shfl_xor_sync(0xFFFFFFFF, pmax_hi, 2));

            float mn_lo = fmaxf(m_lo, pmax_lo);
            float mn_hi = fmaxf(m_hi, pmax_hi);
            al_lo = __expf(m_lo - mn_lo);
            al_hi = __expf(m_hi - mn_hi);
            m_lo = mn_lo; m_hi = mn_hi;

            float sum_lo = 0.f, sum_hi = 0.f;
#pragma unroll
            for (int j = 0; j < 8; j++) {
                int c0 = j * 8 + 2 * tig;
                float p0 = __expf(sacc[j][0] - mn_lo);
                float p1 = __expf(sacc[j][1] - mn_lo);
                float p2 = __expf(sacc[j][2] - mn_hi);
                float p3 = __expf(sacc[j][3] - mn_hi);
                sum_lo += p0 + p1;
                sum_hi += p2 + p3;
                float2 v01; v01.x = tf32r(p0); v01.y = tf32r(p1);
                float2 v23; v23.x = tf32r(p2); v23.y = tf32r(p3);
                *(float2*)(Pw + grp * ATP_PAD + c0)       = v01;
                *(float2*)(Pw + (grp + 8) * ATP_PAD + c0) = v23;
            }
            sum_lo += __shfl_xor_sync(0xFFFFFFFF, sum_lo, 1);
            sum_lo += __shfl_xor_sync(0xFFFFFFFF, sum_lo, 2);
            sum_hi += __shfl_xor_sync(0xFFFFFFFF, sum_hi, 1);
            sum_hi += __shfl_xor_sync(0xFFFFFFFF, sum_hi, 2);
            l_lo = l_lo * al_lo + sum_lo;
            l_hi = l_hi * al_hi + sum_hi;
        } else {
            // ======== DIAGONAL / MASKED TILE ========
            int jmax = limit_max < 0 ? 0 : ((limit_max >> 3) + 1);
            if (jmax > 8) jmax = 8;
            ksmax = jmax;
            float sacc[8][4];
#pragma unroll
            for (int j = 0; j < 8; j++)
#pragma unroll
                for (int c = 0; c < 4; c++) sacc[j][c] = 0.f;

#pragma unroll 4
            for (int ks = 0; ks < 16; ks++) {
                int kc = ks * 8 + tig;
                uint32_t a0 = __float_as_uint(qpA[kc]);
                uint32_t a1 = __float_as_uint(qpA[8 * ATQ_PAD + kc]);
                uint32_t a2 = __float_as_uint(qpA[kc + 4]);
                uint32_t a3 = __float_as_uint(qpA[8 * ATQ_PAD + kc + 4]);
                for (int j = 0; j < jmax; j++) {
                    uint32_t b0 = __float_as_uint(kpB[j * 8 * ATK_PAD + kc]);
                    uint32_t b1 = __float_as_uint(kpB[j * 8 * ATK_PAD + kc + 4]);
                    mma_tf32(sacc[j][0], sacc[j][1], sacc[j][2], sacc[j][3],
                             a0, a1, a2, a3, b0, b1);
                }
            }

            float pmax_lo = NEG_BIG, pmax_hi = NEG_BIG;
            for (int j = 0; j < jmax; j++) {
                int c0 = j * 8 + 2 * tig;
                if (c0     <= r_lo + doff) pmax_lo = fmaxf(pmax_lo, sacc[j][0]);
                if (c0 + 1 <= r_lo + doff) pmax_lo = fmaxf(pmax_lo, sacc[j][1]);
                if (c0     <= r_hi + doff) pmax_hi = fmaxf(pmax_hi, sacc[j][2]);
                if (c0 + 1 <= r_hi + doff) pmax_hi = fmaxf(pmax_hi, sacc[j][3]);
            }
            pmax_lo = fmaxf(pmax_lo, __shfl_xor_sync(0xFFFFFFFF, pmax_lo, 1));
            pmax_lo = fmaxf(pmax_lo, __shfl_xor_sync(0xFFFFFFFF, pmax_lo, 2));
            pmax_hi = fmaxf(pmax_hi, __shfl_xor_sync(0xFFFFFFFF, pmax_hi, 1));
            pmax_hi = fmaxf(pmax_hi, __shfl_xor_sync(0xFFFFFFFF, pmax_hi, 2));

            float mn_lo = fmaxf(m_lo, pmax_lo);
            float mn_hi = fmaxf(m_hi, pmax_hi);
            al_lo = __expf(m_lo - mn_lo);
            al_hi = __expf(m_hi - mn_hi);
            m_lo = mn_lo; m_hi = mn_hi;

            float sum_lo = 0.f, sum_hi = 0.f;
            for (int j = 0; j < jmax; j++) {
                int c0 = j * 8 + 2 * tig;
                float p0 = (c0     <= r_lo + doff) ? __expf(sacc[j][0] - mn_lo) : 0.f;
                float p1 = (c0 + 1 <= r_lo + doff) ? __expf(sacc[j][1] - mn_lo) : 0.f;
                float p2 = (c0     <= r_hi + doff) ? __expf(sacc[j][2] - mn_hi) : 0.f;
                float p3 = (c0 + 1 <= r_hi + doff) ? __expf(sacc[j][3] - mn_hi) : 0.f;
                sum_lo += p0 + p1;
                sum_hi += p2 + p3;
                float2 v01; v01.x = tf32r(p0); v01.y = tf32r(p1);
                float2 v23; v23.x = tf32r(p2); v23.y = tf32r(p3);
                *(float2*)(Pw + grp * ATP_PAD + c0)       = v01;
                *(float2*)(Pw + (grp + 8) * ATP_PAD + c0) = v23;
            }
            sum_lo += __shfl_xor_sync(0xFFFFFFFF, sum_lo, 1);
            sum_lo += __shfl_xor_sync(0xFFFFFFFF, sum_lo, 2);
            sum_hi += __shfl_xor_sync(0xFFFFFFFF, sum_hi, 1);
            sum_hi += __shfl_xor_sync(0xFFFFFFFF, sum_hi, 2);
            l_lo = l_lo * al_lo + sum_lo;
            l_hi = l_hi * al_hi + sum_hi;
        }

        // ---- rescale O; PV (bounded by ksmax) ----
#pragma unroll
        for (int j = 0; j < 16; j++) {
            oacc[j][0] *= al_lo; oacc[j][1] *= al_lo;
            oacc[j][2] *= al_hi; oacc[j][3] *= al_hi;
        }
        __syncwarp();

        if (ksmax == 8) {
#pragma unroll 2
            for (int ks = 0; ks < 8; ks++) {
                int kc = ks * 8 + tig;
                uint32_t a0 = __float_as_uint(Pw[grp * ATP_PAD + kc]);
                uint32_t a1 = __float_as_uint(Pw[(grp + 8) * ATP_PAD + kc]);
                uint32_t a2 = __float_as_uint(Pw[grp * ATP_PAD + kc + 4]);
                uint32_t a3 = __float_as_uint(Pw[(grp + 8) * ATP_PAD + kc + 4]);
                const float* vp0 = Vs + kc * ATV_PAD + grp;
                const float* vp1 = Vs + (kc + 4) * ATV_PAD + grp;
#pragma unroll
                for (int j = 0; j < 16; j++) {
                    uint32_t b0 = __float_as_uint(vp0[j * 8]);
                    uint32_t b1 = __float_as_uint(vp1[j * 8]);
                    mma_tf32(oacc[j][0], oacc[j][1], oacc[j][2], oacc[j][3],
                             a0, a1, a2, a3, b0, b1);
                }
            }
        } else {
            for (int ks = 0; ks < ksmax; ks++) {
                int kc = ks * 8 + tig;
                uint32_t a0 = __float_as_uint(Pw[grp * ATP_PAD + kc]);
                uint32_t a1 = __float_as_uint(Pw[(grp + 8) * ATP_PAD + kc]);
                uint32_t a2 = __float_as_uint(Pw[grp * ATP_PAD + kc + 4]);
                uint32_t a3 = __float_as_uint(Pw[(grp + 8) * ATP_PAD + kc + 4]);
                const float* vp0 = Vs + kc * ATV_PAD + grp;
                const float* vp1 = Vs + (kc + 4) * ATV_PAD + grp;
#pragma unroll
                for (int j = 0; j < 16; j++) {
                    uint32_t b0 = __float_as_uint(vp0[j * 8]);
                    uint32_t b1 = __float_as_uint(vp1[j * 8]);
                    mma_tf32(oacc[j][0], oacc[j][1], oacc[j][2], oacc[j][3],
                             a0, a1, a2, a3, b0, b1);
                }
            }
        }
    }

    // ---- normalize + store ----
    float inv_lo = 1.f / l_lo;
    float inv_hi = 1.f / l_hi;
    float* obase = out + (size_t)(b * SEQ + qrow0) * DMODEL + h * DHEAD;
#pragma unroll
    for (int j = 0; j < 16; j++) {
        int col = j * 8 + 2 * tig;
        float2 o0, o1;
        o0.x = oacc[j][0] * inv_lo; o0.y = oacc[j][1] * inv_lo;
        o1.x = oacc[j][2] * inv_hi; o1.y = oacc[j][3] * inv_hi;
        *(float2*)(obase + (size_t)r_lo * DMODEL + col) = o0;
        *(float2*)(obase + (size_t)r_hi * DMODEL + col) = o1;
    }
}

// ===========================================================================
// Launch
// ===========================================================================
extern "C" void kernel_launch(void* const* d_in, const int* in_sizes, int n_in,
                              void* d_out, int out_size) {
    const float* x     = (const float*)d_in[0];
    const float* w_in  = (const float*)d_in[2];
    const float* b_in  = (const float*)d_in[3];
    const float* w_out = (const float*)d_in[4];
    const float* b_out = (const float*)d_in[5];
    float* out = (float*)d_out;

    float* qkv;   cudaGetSymbolAddress((void**)&qkv,  g_qkv);
    float* attn;  cudaGetSymbolAddress((void**)&attn, g_attn);

    cudaFuncSetAttribute(attn_mma_kernel,
                         cudaFuncAttributeMaxDynamicSharedMemorySize,
                         ATT_SMEM_FLOATS * (int)sizeof(float));
    cudaFuncSetAttribute(mma_gemm_kernel,
                         cudaFuncAttributeMaxDynamicSharedMemorySize,
                         GEMM_SMEM);

    // 1. RoPE tables
    rope_table_kernel<<<(SEQ * 64 + 255) / 256, 256>>>();

    // 2. QKV projection (mma.sync tf32, BK=64, 256 threads)
    mma_gemm_kernel<<<dim3(D3 / 128, (BATCH * SEQ) / 128), 256, GEMM_SMEM>>>(
        x, w_in, b_in, qkv, D3);

    // 3. Flash attention (RoPE fused, warp-local softmax, causal fast path)
    attn_mma_kernel<<<dim3(SEQ / 128, NHEAD, BATCH), 256,
                      ATT_SMEM_FLOATS * sizeof(float)>>>(qkv, attn);

    // 4. Output projection (mma.sync tf32, BK=64, 256 threads)
    mma_gemm_kernel<<<dim3(DMODEL / 128, (BATCH * SEQ) / 128), 256, GEMM_SMEM>>>(
        attn, w_out, b_out, out, DMODEL);
}

// round 16
// speedup vs baseline: 1.5377x; 1.5377x over previous
#include <cuda_runtime.h>
#include <math.h>
#include <stdint.h>

#define BATCH 2
#define SEQ   2048
#define DMODEL 2048
#define NHEAD 16
#define DHEAD 128
#define D3    (3*DMODEL)
#define KDIM  2048

// Scratch (device globals — no allocation allowed)
__device__ float g_qkv[(size_t)BATCH * SEQ * D3];        // [B,S,3D] raw GEMM out
__device__ float g_attn[(size_t)BATCH * SEQ * DMODEL];   // [B,S,D]
__device__ float g_cos[SEQ * 64];
__device__ float g_sin[SEQ * 64];

__device__ __forceinline__ uint32_t f2tf32(float x) {
    uint32_t r;
    asm("cvt.rna.tf32.f32 %0, %1;" : "=r"(r) : "f"(x));
    return r;
}
__device__ __forceinline__ float tf32r(float x) {
    float r;
    asm("cvt.rna.tf32.f32 %0, %1;" : "=f"(r) : "f"(x));
    return r;
}

__device__ __forceinline__ void mma_tf32(float& d0, float& d1, float& d2, float& d3,
                                         uint32_t a0, uint32_t a1, uint32_t a2, uint32_t a3,
                                         uint32_t b0, uint32_t b1) {
    asm volatile(
        "mma.sync.aligned.m16n8k8.row.col.f32.tf32.tf32.f32 "
        "{%0,%1,%2,%3}, {%4,%5,%6,%7}, {%8,%9}, {%0,%1,%2,%3};"
        : "+f"(d0), "+f"(d1), "+f"(d2), "+f"(d3)
        : "r"(a0), "r"(a1), "r"(a2), "r"(a3), "r"(b0), "r"(b1));
}

// ===========================================================================
// mma.sync tf32 GEMM (round-7/9/10 exact — most reproducible fast variant).
// CTA tile 128x128, BK=32, 256 threads (8 warps: 4m x 2n, warp 32x64).
//   A smem [128][AS=36], B smem [32][BS=136] (conflict-free frag reads)
// ===========================================================================
#define BK 32
#define NT (KDIM / BK)
#define AS 36
#define BS 136
#define A_STG (128 * AS)
#define B_STG (32 * BS)
#define STG_FLOATS (A_STG + B_STG)
#define GEMM_SMEM (2 * STG_FLOATS * 4)

__global__ void __launch_bounds__(256, 1)
mma_gemm_kernel(const float* __restrict__ A, const float* __restrict__ W,
                const float* __restrict__ bias, float* __restrict__ C, int N) {
    extern __shared__ float smem[];

    const int tid  = threadIdx.x;
    const int lane = tid & 31;
    const int warp = tid >> 5;
    const int wm   = warp >> 1;
    const int wn   = warp & 1;
    const int grp  = lane >> 2;
    const int tig  = lane & 3;
    const int brow = blockIdx.y;
    const int bcol = blockIdx.x;

    const int ar  = tid >> 3;
    const int ac4 = tid & 7;
    const int bk  = tid >> 5;
    const int bc4 = tid & 31;

    const float* Ag = A + (size_t)(brow * 128 + ar) * KDIM + ac4 * 4;
    const float* Wg = W + (size_t)bk * N + bcol * 128 + bc4 * 4;

    float4 bufA[4], bufB[4];

    auto ldg_chunk = [&](int j) {
        int k0 = j * BK;
#pragma unroll
        for (int i = 0; i < 4; i++)
            bufA[i] = *(const float4*)(Ag + (size_t)(i * 32) * KDIM + k0);
#pragma unroll
        for (int i = 0; i < 4; i++)
            bufB[i] = *(const float4*)(Wg + (size_t)(k0 + i * 8) * N);
    };

    auto sts_chunk = [&](int s) {
        float* sa = smem + s * STG_FLOATS;
        float* sb = sa + A_STG;
#pragma unroll
        for (int i = 0; i < 4; i++) {
            uint4 v;
            v.x = f2tf32(bufA[i].x); v.y = f2tf32(bufA[i].y);
            v.z = f2tf32(bufA[i].z); v.w = f2tf32(bufA[i].w);
            *(uint4*)(sa + (ar + i * 32) * AS + ac4 * 4) = v;
        }
#pragma unroll
        for (int i = 0; i < 4; i++) {
            uint4 v;
            v.x = f2tf32(bufB[i].x); v.y = f2tf32(bufB[i].y);
            v.z = f2tf32(bufB[i].z); v.w = f2tf32(bufB[i].w);
            *(uint4*)(sb + (bk + i * 8) * BS + bc4 * 4) = v;
        }
    };

    float acc[2][8][4];
#pragma unroll
    for (int m = 0; m < 2; m++)
#pragma unroll
        for (int n = 0; n < 8; n++)
#pragma unroll
            for (int c = 0; c < 4; c++) acc[m][n][c] = 0.f;

    ldg_chunk(0);
    sts_chunk(0);
    __syncthreads();

    const int rb0 = wm * 32 + grp;
    const int cb0 = wn * 64 + grp;

    for (int j = 0; j < NT; j++) {
        if (j + 1 < NT) ldg_chunk(j + 1);

        const float* sa = smem + (j & 1) * STG_FLOATS;
        const float* sb = sa + A_STG;
#pragma unroll
        for (int ks = 0; ks < 4; ks++) {
            int kc = ks * 8 + tig;
            uint32_t af[2][4];
#pragma unroll
            for (int m = 0; m < 2; m++) {
                const float* ap = sa + (rb0 + m * 16) * AS + kc;
                af[m][0] = __float_as_uint(ap[0]);
                af[m][1] = __float_as_uint(ap[8 * AS]);
                af[m][2] = __float_as_uint(ap[4]);
                af[m][3] = __float_as_uint(ap[8 * AS + 4]);
            }
            uint32_t bf[8][2];
            const float* bp = sb + kc * BS + cb0;
#pragma unroll
            for (int n = 0; n < 8; n++) {
                bf[n][0] = __float_as_uint(bp[n * 8]);
                bf[n][1] = __float_as_uint(bp[4 * BS + n * 8]);
            }
#pragma unroll
            for (int m = 0; m < 2; m++)
#pragma unroll
                for (int n = 0; n < 8; n++)
                    mma_tf32(acc[m][n][0], acc[m][n][1], acc[m][n][2], acc[m][n][3],
                             af[m][0], af[m][1], af[m][2], af[m][3],
                             bf[n][0], bf[n][1]);
        }

        if (j + 1 < NT) sts_chunk((j + 1) & 1);
        __syncthreads();
    }

#pragma unroll
    for (int m = 0; m < 2; m++) {
        int row0 = brow * 128 + wm * 32 + m * 16 + grp;
#pragma unroll
        for (int n = 0; n < 8; n++) {
            int col = bcol * 128 + wn * 64 + n * 8 + tig * 2;
            float2 bv = *(const float2*)(bias + col);
            float2 o0, o1;
            o0.x = acc[m][n][0] + bv.x; o0.y = acc[m][n][1] + bv.y;
            o1.x = acc[m][n][2] + bv.x; o1.y = acc[m][n][3] + bv.y;
            *(float2*)(C + (size_t)row0 * N + col)       = o0;
            *(float2*)(C + (size_t)(row0 + 8) * N + col) = o1;
        }
    }
}

// ===========================================================================
// RoPE table (cos/sin only; application fused into attention loads)
// ===========================================================================
__global__ void rope_table_kernel() {
    int idx = blockIdx.x * blockDim.x + threadIdx.x;
    if (idx >= SEQ * 64) return;
    int s = idx >> 6;
    int i = idx & 63;
    double theta = exp(-(double)i * log(10000.0) / 64.0);
    float tf = (float)theta;
    float ang = (float)s * tf;
    float sv, cv;
    sincosf(ang, &sv, &cv);
    g_cos[idx] = cv;
    g_sin[idx] = sv;
}

// ===========================================================================
// Flash attention (round-14 exact — verified correct).
// CTA: 128 q-rows (8 warps x 16 rows), kv-tile 64 keys. RoPE fused.
// Causal fast path iff warp's MIN row fully unmasked; jmax clamped to 8.
// ===========================================================================
#define ATQ_PAD 132
#define ATK_PAD 132
#define ATV_PAD 136
#define ATP_PAD 68
#define ATQ_OFF 0
#define ATK_OFF (128 * ATQ_PAD)
#define ATV_OFF (ATK_OFF + 64 * ATK_PAD)
#define ATP_OFF (ATV_OFF + 64 * ATV_PAD)
#define ATT_SMEM_FLOATS (ATP_OFF + 8 * 16 * ATP_PAD)

__global__ void __launch_bounds__(256, 1)
attn_mma_kernel(const float* __restrict__ qkv, float* __restrict__ out) {
    extern __shared__ float sm[];
    float* Qs = sm + ATQ_OFF;
    float* Ks = sm + ATK_OFF;
    float* Vs = sm + ATV_OFF;

    const float SCALE = 0.08838834764831845f;  // 1/sqrt(128)
    const float NEG_BIG = -3.0e38f;

    const int qt = (int)gridDim.x - 1 - (int)blockIdx.x;
    const int h = blockIdx.y, b = blockIdx.z;
    const int tid = threadIdx.x;
    const int lane = tid & 31, warp = tid >> 5;
    const int grp = lane >> 2, tig = lane & 3;

    float* Pw = sm + ATP_OFF + warp * (16 * ATP_PAD);

    const float* qbase = qkv + (size_t)(b * SEQ) * D3 + h * DHEAD;
    const float* kbase = qbase + DMODEL;
    const float* vbase = qbase + 2 * DMODEL;

    const int qrow0 = qt * 128;
    const int r_lo = warp * 16 + grp;
    const int r_hi = r_lo + 8;

    // ---- Load Q with fused RoPE + scale + tf32 round ----
#pragma unroll
    for (int t = 0; t < 8; t++) {
        int lin = tid + t * 256;
        int row = lin >> 4;
        int d0 = (lin & 15) * 4;
        int s = qrow0 + row;
        const float* qp = qbase + (size_t)s * D3;
        float4 q0 = *(const float4*)(qp + d0);
        float4 q1 = *(const float4*)(qp + d0 + 64);
        float4 cv = *(const float4*)(g_cos + s * 64 + d0);
        float4 sv = *(const float4*)(g_sin + s * 64 + d0);
        float4 o0, o1;
        o0.x = tf32r(SCALE * (cv.x * q0.x - sv.x * q1.x));
        o0.y = tf32r(SCALE * (cv.y * q0.y - sv.y * q1.y));
        o0.z = tf32r(SCALE * (cv.z * q0.z - sv.z * q1.z));
        o0.w = tf32r(SCALE * (cv.w * q0.w - sv.w * q1.w));
        o1.x = tf32r(SCALE * (cv.x * q1.x + sv.x * q0.x));
        o1.y = tf32r(SCALE * (cv.y * q1.y + sv.y * q0.y));
        o1.z = tf32r(SCALE * (cv.z * q1.z + sv.z * q0.z));
        o1.w = tf32r(SCALE * (cv.w * q1.w + sv.w * q0.w));
        *(float4*)(Qs + row * ATQ_PAD + d0)      = o0;
        *(float4*)(Qs + row * ATQ_PAD + d0 + 64) = o1;
    }

    float oacc[16][4];
#pragma unroll
    for (int j = 0; j < 16; j++)
#pragma unroll
        for (int c = 0; c < 4; c++) oacc[j][c] = 0.f;

    float m_lo = NEG_BIG, m_hi = NEG_BIG;
    float l_lo = 0.f, l_hi = 0.f;

    const int nkt = 2 * qt + 2;

    for (int kt = 0; kt < nkt; kt++) {
        const int key0 = kt * 64;
        const int doff = qrow0 - key0;

        __syncthreads();

        // ---- Load K with fused RoPE + tf32 round ----
#pragma unroll
        for (int t = 0; t < 4; t++) {
            int lin = tid + t * 256;
            int row = lin >> 4;
            int d0 = (lin & 15) * 4;
            int s = key0 + row;
            const float* kp = kbase + (size_t)s * D3;
            float4 k0 = *(const float4*)(kp + d0);
            float4 k1 = *(const float4*)(kp + d0 + 64);
            float4 cv = *(const float4*)(g_cos + s * 64 + d0);
            float4 sv = *(const float4*)(g_sin + s * 64 + d0);
            float4 o0, o1;
            o0.x = tf32r(cv.x * k0.x - sv.x * k1.x);
            o0.y = tf32r(cv.y * k0.y - sv.y * k1.y);
            o0.z = tf32r(cv.z * k0.z - sv.z * k1.z);
            o0.w = tf32r(cv.w * k0.w - sv.w * k1.w);
            o1.x = tf32r(cv.x * k1.x + sv.x * k0.x);
            o1.y = tf32r(cv.y * k1.y + sv.y * k0.y);
            o1.z = tf32r(cv.z * k1.z + sv.z * k0.z);
            o1.w = tf32r(cv.w * k1.w + sv.w * k0.w);
            *(float4*)(Ks + row * ATK_PAD + d0)      = o0;
            *(float4*)(Ks + row * ATK_PAD + d0 + 64) = o1;
        }
        // ---- Load V with tf32 round ----
#pragma unroll
        for (int t = 0; t < 8; t++) {
            int lin = tid + t * 256;
            int row = lin >> 5;
            int d0 = (lin & 31) * 4;
            float4 vv = *(const float4*)(vbase + (size_t)(key0 + row) * D3 + d0);
            float4 vo;
            vo.x = tf32r(vv.x); vo.y = tf32r(vv.y);
            vo.z = tf32r(vv.z); vo.w = tf32r(vv.w);
            *(float4*)(Vs + row * ATV_PAD + d0) = vo;
        }
        __syncthreads();

        const float* qpA = Qs + r_lo * ATQ_PAD;
        const float* kpB = Ks + grp * ATK_PAD;

        const int limit_min = warp * 16 + doff;
        const int limit_max = limit_min + 15;

        float al_lo, al_hi;
        int ksmax;

        if (limit_min >= 63) {
            // ======== FULL TILE ========
            ksmax = 8;
            float sacc[8][4];
#pragma unroll
            for (int j = 0; j < 8; j++)
#pragma unroll
                for (int c = 0; c < 4; c++) sacc[j][c] = 0.f;

#pragma unroll 4
            for (int ks = 0; ks < 16; ks++) {
                int kc = ks * 8 + tig;
                uint32_t a0 = __float_as_uint(qpA[kc]);
                uint32_t a1 = __float_as_uint(qpA[8 * ATQ_PAD + kc]);
                uint32_t a2 = __float_as_uint(qpA[kc + 4]);
                uint32_t a3 = __float_as_uint(qpA[8 * ATQ_PAD + kc + 4]);
#pragma unroll
                for (int j = 0; j < 8; j++) {
                    uint32_t b0 = __float_as_uint(kpB[j * 8 * ATK_PAD + kc]);
                    uint32_t b1 = __float_as_uint(kpB[j * 8 * ATK_PAD + kc + 4]);
                    mma_tf32(sacc[j][0], sacc[j][1], sacc[j][2], sacc[j][3],
                             a0, a1, a2, a3, b0, b1);
                }
            }

            float pmax_lo = NEG_BIG, pmax_hi = NEG_BIG;
#pragma unroll
            for (int j = 0; j < 8; j++) {
                pmax_lo = fmaxf(pmax_lo, fmaxf(sacc[j][0], sacc[j][1]));
                pmax_hi = fmaxf(pmax_hi, fmaxf(sacc[j][2], sacc[j][3]));
            }
            pmax_lo = fmaxf(pmax_lo, __shfl_xor_sync(0xFFFFFFFF, pmax_lo, 1));
            pmax_lo = fmaxf(pmax_lo, __shfl_xor_sync(0xFFFFFFFF, pmax_lo, 2));
            pmax_hi = fmaxf(pmax_hi, __shfl_xor_sync(0xFFFFFFFF, pmax_hi, 1));
            pmax_hi = fmaxf(pmax_hi, __shfl_xor_sync(0xFFFFFFFF, pmax_hi, 2));

            float mn_lo = fmaxf(m_lo, pmax_lo);
            float mn_hi = fmaxf(m_hi, pmax_hi);
            al_lo = __expf(m_lo - mn_lo);
            al_hi = __expf(m_hi - mn_hi);
            m_lo = mn_lo; m_hi = mn_hi;

            float sum_lo = 0.f, sum_hi = 0.f;
#pragma unroll
            for (int j = 0; j < 8; j++) {
                int c0 = j * 8 + 2 * tig;
                float p0 = __expf(sacc[j][0] - mn_lo);
                float p1 = __expf(sacc[j][1] - mn_lo);
                float p2 = __expf(sacc[j][2] - mn_hi);
                float p3 = __expf(sacc[j][3] - mn_hi);
                sum_lo += p0 + p1;
                sum_hi += p2 + p3;
                float2 v01; v01.x = tf32r(p0); v01.y = tf32r(p1);
                float2 v23; v23.x = tf32r(p2); v23.y = tf32r(p3);
                *(float2*)(Pw + grp * ATP_PAD + c0)       = v01;
                *(float2*)(Pw + (grp + 8) * ATP_PAD + c0) = v23;
            }
            sum_lo += __shfl_xor_sync(0xFFFFFFFF, sum_lo, 1);
            sum_lo += __shfl_xor_sync(0xFFFFFFFF, sum_lo, 2);
            sum_hi += __shfl_xor_sync(0xFFFFFFFF, sum_hi, 1);
            sum_hi += __shfl_xor_sync(0xFFFFFFFF, sum_hi, 2);
            l_lo = l_lo * al_lo + sum_lo;
            l_hi = l_hi * al_hi + sum_hi;
        } else {
            // ======== DIAGONAL / MASKED TILE ========
            int jmax = limit_max < 0 ? 0 : ((limit_max >> 3) + 1);
            if (jmax > 8) jmax = 8;
            ksmax = jmax;
            float sacc[8][4];
#pragma unroll
            for (int j = 0; j < 8; j++)
#pragma unroll
                for (int c = 0; c < 4; c++) sacc[j][c] = 0.f;

#pragma unroll 4
            for (int ks = 0; ks < 16; ks++) {
                int kc = ks * 8 + tig;
                uint32_t a0 = __float_as_uint(qpA[kc]);
                uint32_t a1 = __float_as_uint(qpA[8 * ATQ_PAD + kc]);
                uint32_t a2 = __float_as_uint(qpA[kc + 4]);
                uint32_t a3 = __float_as_uint(qpA[8 * ATQ_PAD + kc + 4]);
                for (int j = 0; j < jmax; j++) {
                    uint32_t b0 = __float_as_uint(kpB[j * 8 * ATK_PAD + kc]);
                    uint32_t b1 = __float_as_uint(kpB[j * 8 * ATK_PAD + kc + 4]);
                    mma_tf32(sacc[j][0], sacc[j][1], sacc[j][2], sacc[j][3],
                             a0, a1, a2, a3, b0, b1);
                }
            }

            float pmax_lo = NEG_BIG, pmax_hi = NEG_BIG;
            for (int j = 0; j < jmax; j++) {
                int c0 = j * 8 + 2 * tig;
                if (c0     <= r_lo + doff) pmax_lo = fmaxf(pmax_lo, sacc[j][0]);
                if (c0 + 1 <= r_lo + doff) pmax_lo = fmaxf(pmax_lo, sacc[j][1]);
                if (c0     <= r_hi + doff) pmax_hi = fmaxf(pmax_hi, sacc[j][2]);
                if (c0 + 1 <= r_hi + doff) pmax_hi = fmaxf(pmax_hi, sacc[j][3]);
            }
            pmax_lo = fmaxf(pmax_lo, __shfl_xor_sync(0xFFFFFFFF, pmax_lo, 1));
            pmax_lo = fmaxf(pmax_lo, __shfl_xor_sync(0xFFFFFFFF, pmax_lo, 2));
            pmax_hi = fmaxf(pmax_hi, __shfl_xor_sync(0xFFFFFFFF, pmax_hi, 1));
            pmax_hi = fmaxf(pmax_hi, __shfl_xor_sync(0xFFFFFFFF, pmax_hi, 2));

            float mn_lo = fmaxf(m_lo, pmax_lo);
            float mn_hi = fmaxf(m_hi, pmax_hi);
            al_lo = __expf(m_lo - mn_lo);
            al_hi = __expf(m_hi - mn_hi);
            m_lo = mn_lo; m_hi = mn_hi;

            float sum_lo = 0.f, sum_hi = 0.f;
            for (int j = 0; j < jmax; j++) {
                int c0 = j * 8 + 2 * tig;
                float p0 = (c0     <= r_lo + doff) ? __expf(sacc[j][0] - mn_lo) : 0.f;
                float p1 = (c0 + 1 <= r_lo + doff) ? __expf(sacc[j][1] - mn_lo) : 0.f;
                float p2 = (c0     <= r_hi + doff) ? __expf(sacc[j][2] - mn_hi) : 0.f;
                float p3 = (c0 + 1 <= r_hi + doff) ? __expf(sacc[j][3] - mn_hi) : 0.f;
                sum_lo += p0 + p1;
                sum_hi += p2 + p3;
                float2 v01; v01.x = tf32r(p0); v01.y = tf32r(p1);
                float2 v23; v23.x = tf32r(p2); v23.y = tf32r(p3);
                *(float2*)(Pw + grp * ATP_PAD + c0)       = v01;
                *(float2*)(Pw + (grp + 8) * ATP_PAD + c0) = v23;
            }
            sum_lo += __shfl_xor_sync(0xFFFFFFFF, sum_lo, 1);
            sum_lo += __shfl_xor_sync(0xFFFFFFFF, sum_lo, 2);
            sum_hi += __shfl_xor_sync(0xFFFFFFFF, sum_hi, 1);
            sum_hi += __shfl_xor_sync(0xFFFFFFFF, sum_hi, 2);
            l_lo = l_lo * al_lo + sum_lo;
            l_hi = l_hi * al_hi + sum_hi;
        }

        // ---- rescale O; PV (bounded by ksmax) ----
#pragma unroll
        for (int j = 0; j < 16; j++) {
            oacc[j][0] *= al_lo; oacc[j][1] *= al_lo;
            oacc[j][2] *= al_hi; oacc[j][3] *= al_hi;
        }
        __syncwarp();

        if (ksmax == 8) {
#pragma unroll 2
            for (int ks = 0; ks < 8; ks++) {
                int kc = ks * 8 + tig;
                uint32_t a0 = __float_as_uint(Pw[grp * ATP_PAD + kc]);
                uint32_t a1 = __float_as_uint(Pw[(grp + 8) * ATP_PAD + kc]);
                uint32_t a2 = __float_as_uint(Pw[grp * ATP_PAD + kc + 4]);
                uint32_t a3 = __float_as_uint(Pw[(grp + 8) * ATP_PAD + kc + 4]);
                const float* vp0 = Vs + kc * ATV_PAD + grp;
                const float* vp1 = Vs + (kc + 4) * ATV_PAD + grp;
#pragma unroll
                for (int j = 0; j < 16; j++) {
                    uint32_t b0 = __float_as_uint(vp0[j * 8]);
                    uint32_t b1 = __float_as_uint(vp1[j * 8]);
                    mma_tf32(oacc[j][0], oacc[j][1], oacc[j][2], oacc[j][3],
                             a0, a1, a2, a3, b0, b1);
                }
            }
        } else {
            for (int ks = 0; ks < ksmax; ks++) {
                int kc = ks * 8 + tig;
                uint32_t a0 = __float_as_uint(Pw[grp * ATP_PAD + kc]);
                uint32_t a1 = __float_as_uint(Pw[(grp + 8) * ATP_PAD + kc]);
                uint32_t a2 = __float_as_uint(Pw[grp * ATP_PAD + kc + 4]);
                uint32_t a3 = __float_as_uint(Pw[(grp + 8) * ATP_PAD + kc + 4]);
                const float* vp0 = Vs + kc * ATV_PAD + grp;
                const float* vp1 = Vs + (kc + 4) * ATV_PAD + grp;
#pragma unroll
                for (int j = 0; j < 16; j++) {
                    uint32_t b0 = __float_as_uint(vp0[j * 8]);
                    uint32_t b1 = __float_as_uint(vp1[j * 8]);
                    mma_tf32(oacc[j][0], oacc[j][1], oacc[j][2], oacc[j][3],
                             a0, a1, a2, a3, b0, b1);
                }
            }
        }
    }

    // ---- normalize + store ----
    float inv_lo = 1.f / l_lo;
    float inv_hi = 1.f / l_hi;
    float* obase = out + (size_t)(b * SEQ + qrow0) * DMODEL + h * DHEAD;
#pragma unroll
    for (int j = 0; j < 16; j++) {
        int col = j * 8 + 2 * tig;
        float2 o0, o1;
        o0.x = oacc[j][0] * inv_lo; o0.y = oacc[j][1] * inv_lo;
        o1.x = oacc[j][2] * inv_hi; o1.y = oacc[j][3] * inv_hi;
        *(float2*)(obase + (size_t)r_lo * DMODEL + col) = o0;
        *(float2*)(obase + (size_t)r_hi * DMODEL + col) = o1;
    }
}

// ===========================================================================
// Launch
// ===========================================================================
extern "C" void kernel_launch(void* const* d_in, const int* in_sizes, int n_in,
                              void* d_out, int out_size) {
    const float* x     = (const float*)d_in[0];
    const float* w_in  = (const float*)d_in[2];
    const float* b_in  = (const float*)d_in[3];
    const float* w_out = (const float*)d_in[4];
    const float* b_out = (const float*)d_in[5];
    float* out = (float*)d_out;

    float* qkv;   cudaGetSymbolAddress((void**)&qkv,  g_qkv);
    float* attn;  cudaGetSymbolAddress((void**)&attn, g_attn);

    cudaFuncSetAttribute(attn_mma_kernel,
                         cudaFuncAttributeMaxDynamicSharedMemorySize,
                         ATT_SMEM_FLOATS * (int)sizeof(float));
    cudaFuncSetAttribute(mma_gemm_kernel,
                         cudaFuncAttributeMaxDynamicSharedMemorySize,
                         GEMM_SMEM);

    // 1. RoPE tables
    rope_table_kernel<<<(SEQ * 64 + 255) / 256, 256>>>();

    // 2. QKV projection (mma.sync tf32, BK=32, 256 threads)
    mma_gemm_kernel<<<dim3(D3 / 128, (BATCH * SEQ) / 128), 256, GEMM_SMEM>>>(
        x, w_in, b_in, qkv, D3);

    // 3. Flash attention (RoPE fused, warp-local softmax, causal fast path)
    attn_mma_kernel<<<dim3(SEQ / 128, NHEAD, BATCH), 256,
                      ATT_SMEM_FLOATS * sizeof(float)>>>(qkv, attn);

    // 4. Output projection (mma.sync tf32, BK=32, 256 threads)
    mma_gemm_kernel<<<dim3(DMODEL / 128, (BATCH * SEQ) / 128), 256, GEMM_SMEM>>>(
        attn, w_out, b_out, out, DMODEL);
}

// round 17
// speedup vs baseline: 1.9878x; 1.2927x over previous
#include <cuda_runtime.h>
#include <cuda_fp16.h>
#include <math.h>
#include <stdint.h>

#define BATCH 2
#define SEQ   2048
#define DMODEL 2048
#define NHEAD 16
#define DHEAD 128
#define D3    (3*DMODEL)
#define KDIM  2048

// Scratch (device globals — no allocation allowed)
__device__ float g_qkv[(size_t)BATCH * SEQ * D3];        // [B,S,3D] raw GEMM out
__device__ float g_attn[(size_t)BATCH * SEQ * DMODEL];   // [B,S,D]
__device__ float g_cos[SEQ * 64];
__device__ float g_sin[SEQ * 64];

__device__ __forceinline__ float tf32r(float x) {
    float r;
    asm("cvt.rna.tf32.f32 %0, %1;" : "=f"(r) : "f"(x));
    return r;
}
__device__ __forceinline__ uint32_t packh2(float lo, float hi) {
    __half2 h = __floats2half2_rn(lo, hi);
    return *(uint32_t*)&h;
}

__device__ __forceinline__ void mma_tf32(float& d0, float& d1, float& d2, float& d3,
                                         uint32_t a0, uint32_t a1, uint32_t a2, uint32_t a3,
                                         uint32_t b0, uint32_t b1) {
    asm volatile(
        "mma.sync.aligned.m16n8k8.row.col.f32.tf32.tf32.f32 "
        "{%0,%1,%2,%3}, {%4,%5,%6,%7}, {%8,%9}, {%0,%1,%2,%3};"
        : "+f"(d0), "+f"(d1), "+f"(d2), "+f"(d3)
        : "r"(a0), "r"(a1), "r"(a2), "r"(a3), "r"(b0), "r"(b1));
}
__device__ __forceinline__ void mma_f16(float& d0, float& d1, float& d2, float& d3,
                                        uint32_t a0, uint32_t a1, uint32_t a2, uint32_t a3,
                                        uint32_t b0, uint32_t b1) {
    asm volatile(
        "mma.sync.aligned.m16n8k16.row.col.f32.f16.f16.f32 "
        "{%0,%1,%2,%3}, {%4,%5,%6,%7}, {%8,%9}, {%0,%1,%2,%3};"
        : "+f"(d0), "+f"(d1), "+f"(d2), "+f"(d3)
        : "r"(a0), "r"(a1), "r"(a2), "r"(a3), "r"(b0), "r"(b1));
}

// ===========================================================================
// fp16 mma.sync GEMM: C[M,N] = A[M,2048] @ W[2048,N] + bias[N], fp32 accum.
// CTA tile 128x128, BK=32 (2 x k16 steps), 256 threads, 8 warps (4m x 2n),
// warp tile 32x64. Double-buffered.
//   A smem [128 rows][20 u32 words]  (word = half2 k-pair; bank 20g+t distinct)
//   B smem [16 pairs][136 u32 words] (bank 8t+g distinct)
// ===========================================================================
#define BK 32
#define NT (KDIM / BK)
#define APADH 20
#define BPADH 136
#define A_WORDS (128 * APADH)          // 2560
#define B_WORDS (16 * BPADH)           // 2176
#define STGH (A_WORDS + B_WORDS)       // 4736 words
#define GEMM_SMEM (2 * STGH * 4)       // 37888 B

__global__ void __launch_bounds__(256, 1)
mma_gemm_kernel(const float* __restrict__ A, const float* __restrict__ W,
                const float* __restrict__ bias, float* __restrict__ C, int N) {
    extern __shared__ uint32_t smem[];

    const int tid  = threadIdx.x;
    const int lane = tid & 31;
    const int warp = tid >> 5;
    const int wm   = warp >> 1;          // 0..3
    const int wn   = warp & 1;           // 0..1
    const int grp  = lane >> 2;
    const int tig  = lane & 3;
    const int brow = blockIdx.y;
    const int bcol = blockIdx.x;

    // A loader: rows ar+i*32 (i=0..3), float4 col ac4
    const int ar  = tid >> 3;
    const int ac4 = tid & 7;
    // B loader: pair p and p+8, n-float4 col nc4
    const int bp_ = tid >> 5;            // 0..7
    const int nc4 = tid & 31;

    const float* Ag = A + (size_t)(brow * 128 + ar) * KDIM + ac4 * 4;
    const float* Wg = W + (size_t)(2 * bp_) * N + bcol * 128 + nc4 * 4;

    float4 bufA[4];
    float4 bufB[4];   // [0,1] = rows 2p,2p+1 ; [2,3] = rows 2p+16, 2p+17

    auto ldg_chunk = [&](int j) {
        int k0 = j * BK;
#pragma unroll
        for (int i = 0; i < 4; i++)
            bufA[i] = *(const float4*)(Ag + (size_t)(i * 32) * KDIM + k0);
        bufB[0] = *(const float4*)(Wg + (size_t)(k0)      * N);
        bufB[1] = *(const float4*)(Wg + (size_t)(k0 + 1)  * N);
        bufB[2] = *(const float4*)(Wg + (size_t)(k0 + 16) * N);
        bufB[3] = *(const float4*)(Wg + (size_t)(k0 + 17) * N);
    };

    auto sts_chunk = [&](int s) {
        uint32_t* sa = smem + s * STGH;
        uint32_t* sb = sa + A_WORDS;
#pragma unroll
        for (int i = 0; i < 4; i++) {
            uint2 w;
            w.x = packh2(bufA[i].x, bufA[i].y);
            w.y = packh2(bufA[i].z, bufA[i].w);
            *(uint2*)(sa + (ar + i * 32) * APADH + ac4 * 2) = w;
        }
        {
            uint4 w;
            w.x = packh2(bufB[0].x, bufB[1].x);
            w.y = packh2(bufB[0].y, bufB[1].y);
            w.z = packh2(bufB[0].z, bufB[1].z);
            w.w = packh2(bufB[0].w, bufB[1].w);
            *(uint4*)(sb + bp_ * BPADH + nc4 * 4) = w;
            uint4 v;
            v.x = packh2(bufB[2].x, bufB[3].x);
            v.y = packh2(bufB[2].y, bufB[3].y);
            v.z = packh2(bufB[2].z, bufB[3].z);
            v.w = packh2(bufB[2].w, bufB[3].w);
            *(uint4*)(sb + (bp_ + 8) * BPADH + nc4 * 4) = v;
        }
    };

    float acc[2][8][4];
#pragma unroll
    for (int m = 0; m < 2; m++)
#pragma unroll
        for (int n = 0; n < 8; n++)
#pragma unroll
            for (int c = 0; c < 4; c++) acc[m][n][c] = 0.f;

    ldg_chunk(0);
    sts_chunk(0);
    __syncthreads();

    const int rb0 = wm * 32 + grp;
    const int cb0 = wn * 64 + grp;

    for (int j = 0; j < NT; j++) {
        if (j + 1 < NT) ldg_chunk(j + 1);

        const uint32_t* sa = smem + (j & 1) * STGH;
        const uint32_t* sb = sa + A_WORDS;
#pragma unroll
        for (int s = 0; s < 2; s++) {
            uint32_t af[2][4];
#pragma unroll
            for (int m = 0; m < 2; m++) {
                const uint32_t* ap = sa + (rb0 + m * 16) * APADH + s * 8 + tig;
                af[m][0] = ap[0];
                af[m][1] = ap[8 * APADH];
                af[m][2] = ap[4];
                af[m][3] = ap[8 * APADH + 4];
            }
            uint32_t bf[8][2];
            const uint32_t* bpt = sb + (s * 8 + tig) * BPADH + cb0;
#pragma unroll
            for (int n = 0; n < 8; n++) {
                bf[n][0] = bpt[n * 8];
                bf[n][1] = bpt[4 * BPADH + n * 8];
            }
#pragma unroll
            for (int m = 0; m < 2; m++)
#pragma unroll
                for (int n = 0; n < 8; n++)
                    mma_f16(acc[m][n][0], acc[m][n][1], acc[m][n][2], acc[m][n][3],
                            af[m][0], af[m][1], af[m][2], af[m][3],
                            bf[n][0], bf[n][1]);
        }

        if (j + 1 < NT) sts_chunk((j + 1) & 1);
        __syncthreads();
    }

    // Epilogue (C fragment layout identical to k8 variant)
#pragma unroll
    for (int m = 0; m < 2; m++) {
        int row0 = brow * 128 + wm * 32 + m * 16 + grp;
#pragma unroll
        for (int n = 0; n < 8; n++) {
            int col = bcol * 128 + wn * 64 + n * 8 + tig * 2;
            float2 bv = *(const float2*)(bias + col);
            float2 o0, o1;
            o0.x = acc[m][n][0] + bv.x; o0.y = acc[m][n][1] + bv.y;
            o1.x = acc[m][n][2] + bv.x; o1.y = acc[m][n][3] + bv.y;
            *(float2*)(C + (size_t)row0 * N + col)       = o0;
            *(float2*)(C + (size_t)(row0 + 8) * N + col) = o1;
        }
    }
}

// ===========================================================================
// RoPE table (cos/sin only; application fused into attention loads)
// ===========================================================================
__global__ void rope_table_kernel() {
    int idx = blockIdx.x * blockDim.x + threadIdx.x;
    if (idx >= SEQ * 64) return;
    int s = idx >> 6;
    int i = idx & 63;
    double theta = exp(-(double)i * log(10000.0) / 64.0);
    float tf = (float)theta;
    float ang = (float)s * tf;
    float sv, cv;
    sincosf(ang, &sv, &cv);
    g_cos[idx] = cv;
    g_sin[idx] = sv;
}

// ===========================================================================
// Flash attention (round-14/16 exact — verified correct, tf32).
// CTA: 128 q-rows (8 warps x 16 rows), kv-tile 64 keys. RoPE fused.
// Causal fast path iff warp's MIN row fully unmasked; jmax clamped to 8.
// ===========================================================================
#define ATQ_PAD 132
#define ATK_PAD 132
#define ATV_PAD 136
#define ATP_PAD 68
#define ATQ_OFF 0
#define ATK_OFF (128 * ATQ_PAD)
#define ATV_OFF (ATK_OFF + 64 * ATK_PAD)
#define ATP_OFF (ATV_OFF + 64 * ATV_PAD)
#define ATT_SMEM_FLOATS (ATP_OFF + 8 * 16 * ATP_PAD)

__global__ void __launch_bounds__(256, 1)
attn_mma_kernel(const float* __restrict__ qkv, float* __restrict__ out) {
    extern __shared__ float sm[];
    float* Qs = sm + ATQ_OFF;
    float* Ks = sm + ATK_OFF;
    float* Vs = sm + ATV_OFF;

    const float SCALE = 0.08838834764831845f;  // 1/sqrt(128)
    const float NEG_BIG = -3.0e38f;

    const int qt = (int)gridDim.x - 1 - (int)blockIdx.x;
    const int h = blockIdx.y, b = blockIdx.z;
    const int tid = threadIdx.x;
    const int lane = tid & 31, warp = tid >> 5;
    const int grp = lane >> 2, tig = lane & 3;

    float* Pw = sm + ATP_OFF + warp * (16 * ATP_PAD);

    const float* qbase = qkv + (size_t)(b * SEQ) * D3 + h * DHEAD;
    const float* kbase = qbase + DMODEL;
    const float* vbase = qbase + 2 * DMODEL;

    const int qrow0 = qt * 128;
    const int r_lo = warp * 16 + grp;
    const int r_hi = r_lo + 8;

    // ---- Load Q with fused RoPE + scale + tf32 round ----
#pragma unroll
    for (int t = 0; t < 8; t++) {
        int lin = tid + t * 256;
        int row = lin >> 4;
        int d0 = (lin & 15) * 4;
        int s = qrow0 + row;
        const float* qp = qbase + (size_t)s * D3;
        float4 q0 = *(const float4*)(qp + d0);
        float4 q1 = *(const float4*)(qp + d0 + 64);
        float4 cv = *(const float4*)(g_cos + s * 64 + d0);
        float4 sv = *(const float4*)(g_sin + s * 64 + d0);
        float4 o0, o1;
        o0.x = tf32r(SCALE * (cv.x * q0.x - sv.x * q1.x));
        o0.y = tf32r(SCALE * (cv.y * q0.y - sv.y * q1.y));
        o0.z = tf32r(SCALE * (cv.z * q0.z - sv.z * q1.z));
        o0.w = tf32r(SCALE * (cv.w * q0.w - sv.w * q1.w));
        o1.x = tf32r(SCALE * (cv.x * q1.x + sv.x * q0.x));
        o1.y = tf32r(SCALE * (cv.y * q1.y + sv.y * q0.y));
        o1.z = tf32r(SCALE * (cv.z * q1.z + sv.z * q0.z));
        o1.w = tf32r(SCALE * (cv.w * q1.w + sv.w * q0.w));
        *(float4*)(Qs + row * ATQ_PAD + d0)      = o0;
        *(float4*)(Qs + row * ATQ_PAD + d0 + 64) = o1;
    }

    float oacc[16][4];
#pragma unroll
    for (int j = 0; j < 16; j++)
#pragma unroll
        for (int c = 0; c < 4; c++) oacc[j][c] = 0.f;

    float m_lo = NEG_BIG, m_hi = NEG_BIG;
    float l_lo = 0.f, l_hi = 0.f;

    const int nkt = 2 * qt + 2;

    for (int kt = 0; kt < nkt; kt++) {
        const int key0 = kt * 64;
        const int doff = qrow0 - key0;

        __syncthreads();

        // ---- Load K with fused RoPE + tf32 round ----
#pragma unroll
        for (int t = 0; t < 4; t++) {
            int lin = tid + t * 256;
            int row = lin >> 4;
            int d0 = (lin & 15) * 4;
            int s = key0 + row;
            const float* kp = kbase + (size_t)s * D3;
            float4 k0 = *(const float4*)(kp + d0);
            float4 k1 = *(const float4*)(kp + d0 + 64);
            float4 cv = *(const float4*)(g_cos + s * 64 + d0);
            float4 sv = *(const float4*)(g_sin + s * 64 + d0);
            float4 o0, o1;
            o0.x = tf32r(cv.x * k0.x - sv.x * k1.x);
            o0.y = tf32r(cv.y * k0.y - sv.y * k1.y);
            o0.z = tf32r(cv.z * k0.z - sv.z * k1.z);
            o0.w = tf32r(cv.w * k0.w - sv.w * k1.w);
            o1.x = tf32r(cv.x * k1.x + sv.x * k0.x);
            o1.y = tf32r(cv.y * k1.y + sv.y * k0.y);
            o1.z = tf32r(cv.z * k1.z + sv.z * k0.z);
            o1.w = tf32r(cv.w * k1.w + sv.w * k0.w);
            *(float4*)(Ks + row * ATK_PAD + d0)      = o0;
            *(float4*)(Ks + row * ATK_PAD + d0 + 64) = o1;
        }
        // ---- Load V with tf32 round ----
#pragma unroll
        for (int t = 0; t < 8; t++) {
            int lin = tid + t * 256;
            int row = lin >> 5;
            int d0 = (lin & 31) * 4;
            float4 vv = *(const float4*)(vbase + (size_t)(key0 + row) * D3 + d0);
            float4 vo;
            vo.x = tf32r(vv.x); vo.y = tf32r(vv.y);
            vo.z = tf32r(vv.z); vo.w = tf32r(vv.w);
            *(float4*)(Vs + row * ATV_PAD + d0) = vo;
        }
        __syncthreads();

        const float* qpA = Qs + r_lo * ATQ_PAD;
        const float* kpB = Ks + grp * ATK_PAD;

        const int limit_min = warp * 16 + doff;
        const int limit_max = limit_min + 15;

        float al_lo, al_hi;
        int ksmax;

        if (limit_min >= 63) {
            // ======== FULL TILE ========
            ksmax = 8;
            float sacc[8][4];
#pragma unroll
            for (int j = 0; j < 8; j++)
#pragma unroll
                for (int c = 0; c < 4; c++) sacc[j][c] = 0.f;

#pragma unroll 4
            for (int ks = 0; ks < 16; ks++) {
                int kc = ks * 8 + tig;
                uint32_t a0 = __float_as_uint(qpA[kc]);
                uint32_t a1 = __float_as_uint(qpA[8 * ATQ_PAD + kc]);
                uint32_t a2 = __float_as_uint(qpA[kc + 4]);
                uint32_t a3 = __float_as_uint(qpA[8 * ATQ_PAD + kc + 4]);
#pragma unroll
                for (int j = 0; j < 8; j++) {
                    uint32_t b0 = __float_as_uint(kpB[j * 8 * ATK_PAD + kc]);
                    uint32_t b1 = __float_as_uint(kpB[j * 8 * ATK_PAD + kc + 4]);
                    mma_tf32(sacc[j][0], sacc[j][1], sacc[j][2], sacc[j][3],
                             a0, a1, a2, a3, b0, b1);
                }
            }

            float pmax_lo = NEG_BIG, pmax_hi = NEG_BIG;
#pragma unroll
            for (int j = 0; j < 8; j++) {
                pmax_lo = fmaxf(pmax_lo, fmaxf(sacc[j][0], sacc[j][1]));
                pmax_hi = fmaxf(pmax_hi, fmaxf(sacc[j][2], sacc[j][3]));
            }
            pmax_lo = fmaxf(pmax_lo, __shfl_xor_sync(0xFFFFFFFF, pmax_lo, 1));
            pmax_lo = fmaxf(pmax_lo, __shfl_xor_sync(0xFFFFFFFF, pmax_lo, 2));
            pmax_hi = fmaxf(pmax_hi, __shfl_xor_sync(0xFFFFFFFF, pmax_hi, 1));
            pmax_hi = fmaxf(pmax_hi, __shfl_xor_sync(0xFFFFFFFF, pmax_hi, 2));

            float mn_lo = fmaxf(m_lo, pmax_lo);
            float mn_hi = fmaxf(m_hi, pmax_hi);
            al_lo = __expf(m_lo - mn_lo);
            al_hi = __expf(m_hi - mn_hi);
            m_lo = mn_lo; m_hi = mn_hi;

            float sum_lo = 0.f, sum_hi = 0.f;
#pragma unroll
            for (int j = 0; j < 8; j++) {
                int c0 = j * 8 + 2 * tig;
                float p0 = __expf(sacc[j][0] - mn_lo);
                float p1 = __expf(sacc[j][1] - mn_lo);
                float p2 = __expf(sacc[j][2] - mn_hi);
                float p3 = __expf(sacc[j][3] - mn_hi);
                sum_lo += p0 + p1;
                sum_hi += p2 + p3;
                float2 v01; v01.x = tf32r(p0); v01.y = tf32r(p1);
                float2 v23; v23.x = tf32r(p2); v23.y = tf32r(p3);
                *(float2*)(Pw + grp * ATP_PAD + c0)       = v01;
                *(float2*)(Pw + (grp + 8) * ATP_PAD + c0) = v23;
            }
            sum_lo += __shfl_xor_sync(0xFFFFFFFF, sum_lo, 1);
            sum_lo += __shfl_xor_sync(0xFFFFFFFF, sum_lo, 2);
            sum_hi += __shfl_xor_sync(0xFFFFFFFF, sum_hi, 1);
            sum_hi += __shfl_xor_sync(0xFFFFFFFF, sum_hi, 2);
            l_lo = l_lo * al_lo + sum_lo;
            l_hi = l_hi * al_hi + sum_hi;
        } else {
            // ======== DIAGONAL / MASKED TILE ========
            int jmax = limit_max < 0 ? 0 : ((limit_max >> 3) + 1);
            if (jmax > 8) jmax = 8;
            ksmax = jmax;
            float sacc[8][4];
#pragma unroll
            for (int j = 0; j < 8; j++)
#pragma unroll
                for (int c = 0; c < 4; c++) sacc[j][c] = 0.f;

#pragma unroll 4
            for (int ks = 0; ks < 16; ks++) {
                int kc = ks * 8 + tig;
                uint32_t a0 = __float_as_uint(qpA[kc]);
                uint32_t a1 = __float_as_uint(qpA[8 * ATQ_PAD + kc]);
                uint32_t a2 = __float_as_uint(qpA[kc + 4]);
                uint32_t a3 = __float_as_uint(qpA[8 * ATQ_PAD + kc + 4]);
                for (int j = 0; j < jmax; j++) {
                    uint32_t b0 = __float_as_uint(kpB[j * 8 * ATK_PAD + kc]);
                    uint32_t b1 = __float_as_uint(kpB[j * 8 * ATK_PAD + kc + 4]);
                    mma_tf32(sacc[j][0], sacc[j][1], sacc[j][2], sacc[j][3],
                             a0, a1, a2, a3, b0, b1);
                }
            }

            float pmax_lo = NEG_BIG, pmax_hi = NEG_BIG;
            for (int j = 0; j < jmax; j++) {
                int c0 = j * 8 + 2 * tig;
                if (c0     <= r_lo + doff) pmax_lo = fmaxf(pmax_lo, sacc[j][0]);
                if (c0 + 1 <= r_lo + doff) pmax_lo = fmaxf(pmax_lo, sacc[j][1]);
                if (c0     <= r_hi + doff) pmax_hi = fmaxf(pmax_hi, sacc[j][2]);
                if (c0 + 1 <= r_hi + doff) pmax_hi = fmaxf(pmax_hi, sacc[j][3]);
            }
            pmax_lo = fmaxf(pmax_lo, __shfl_xor_sync(0xFFFFFFFF, pmax_lo, 1));
            pmax_lo = fmaxf(pmax_lo, __shfl_xor_sync(0xFFFFFFFF, pmax_lo, 2));
            pmax_hi = fmaxf(pmax_hi, __shfl_xor_sync(0xFFFFFFFF, pmax_hi, 1));
            pmax_hi = fmaxf(pmax_hi, __shfl_xor_sync(0xFFFFFFFF, pmax_hi, 2));

            float mn_lo = fmaxf(m_lo, pmax_lo);
            float mn_hi = fmaxf(m_hi, pmax_hi);
            al_lo = __expf(m_lo - mn_lo);
            al_hi = __expf(m_hi - mn_hi);
            m_lo = mn_lo; m_hi = mn_hi;

            float sum_lo = 0.f, sum_hi = 0.f;
            for (int j = 0; j < jmax; j++) {
                int c0 = j * 8 + 2 * tig;
                float p0 = (c0     <= r_lo + doff) ? __expf(sacc[j][0] - mn_lo) : 0.f;
                float p1 = (c0 + 1 <= r_lo + doff) ? __expf(sacc[j][1] - mn_lo) : 0.f;
                float p2 = (c0     <= r_hi + doff) ? __expf(sacc[j][2] - mn_hi) : 0.f;
                float p3 = (c0 + 1 <= r_hi + doff) ? __expf(sacc[j][3] - mn_hi) : 0.f;
                sum_lo += p0 + p1;
                sum_hi += p2 + p3;
                float2 v01; v01.x = tf32r(p0); v01.y = tf32r(p1);
                float2 v23; v23.x = tf32r(p2); v23.y = tf32r(p3);
                *(float2*)(Pw + grp * ATP_PAD + c0)       = v01;
                *(float2*)(Pw + (grp + 8) * ATP_PAD + c0) = v23;
            }
            sum_lo += __shfl_xor_sync(0xFFFFFFFF, sum_lo, 1);
            sum_lo += __shfl_xor_sync(0xFFFFFFFF, sum_lo, 2);
            sum_hi += __shfl_xor_sync(0xFFFFFFFF, sum_hi, 1);
            sum_hi += __shfl_xor_sync(0xFFFFFFFF, sum_hi, 2);
            l_lo = l_lo * al_lo + sum_lo;
            l_hi = l_hi * al_hi + sum_hi;
        }

        // ---- rescale O; PV (bounded by ksmax) ----
#pragma unroll
        for (int j = 0; j < 16; j++) {
            oacc[j][0] *= al_lo; oacc[j][1] *= al_lo;
            oacc[j][2] *= al_hi; oacc[j][3] *= al_hi;
        }
        __syncwarp();

        if (ksmax == 8) {
#pragma unroll 2
            for (int ks = 0; ks < 8; ks++) {
                int kc = ks * 8 + tig;
                uint32_t a0 = __float_as_uint(Pw[grp * ATP_PAD + kc]);
                uint32_t a1 = __float_as_uint(Pw[(grp + 8) * ATP_PAD + kc]);
                uint32_t a2 = __float_as_uint(Pw[grp * ATP_PAD + kc + 4]);
                uint32_t a3 = __float_as_uint(Pw[(grp + 8) * ATP_PAD + kc + 4]);
                const float* vp0 = Vs + kc * ATV_PAD + grp;
                const float* vp1 = Vs + (kc + 4) * ATV_PAD + grp;
#pragma unroll
                for (int j = 0; j < 16; j++) {
                    uint32_t b0 = __float_as_uint(vp0[j * 8]);
                    uint32_t b1 = __float_as_uint(vp1[j * 8]);
                    mma_tf32(oacc[j][0], oacc[j][1], oacc[j][2], oacc[j][3],
                             a0, a1, a2, a3, b0, b1);
                }
            }
        } else {
            for (int ks = 0; ks < ksmax; ks++) {
                int kc = ks * 8 + tig;
                uint32_t a0 = __float_as_uint(Pw[grp * ATP_PAD + kc]);
                uint32_t a1 = __float_as_uint(Pw[(grp + 8) * ATP_PAD + kc]);
                uint32_t a2 = __float_as_uint(Pw[grp * ATP_PAD + kc + 4]);
                uint32_t a3 = __float_as_uint(Pw[(grp + 8) * ATP_PAD + kc + 4]);
                const float* vp0 = Vs + kc * ATV_PAD + grp;
                const float* vp1 = Vs + (kc + 4) * ATV_PAD + grp;
#pragma unroll
                for (int j = 0; j < 16; j++) {
                    uint32_t b0 = __float_as_uint(vp0[j * 8]);
                    uint32_t b1 = __float_as_uint(vp1[j * 8]);
                    mma_tf32(oacc[j][0], oacc[j][1], oacc[j][2], oacc[j][3],
                             a0, a1, a2, a3, b0, b1);
                }
            }
        }
    }

    // ---- normalize + store ----
    float inv_lo = 1.f / l_lo;
    float inv_hi = 1.f / l_hi;
    float* obase = out + (size_t)(b * SEQ + qrow0) * DMODEL + h * DHEAD;
#pragma unroll
    for (int j = 0; j < 16; j++) {
        int col = j * 8 + 2 * tig;
        float2 o0, o1;
        o0.x = oacc[j][0] * inv_lo; o0.y = oacc[j][1] * inv_lo;
        o1.x = oacc[j][2] * inv_hi; o1.y = oacc[j][3] * inv_hi;
        *(float2*)(obase + (size_t)r_lo * DMODEL + col) = o0;
        *(float2*)(obase + (size_t)r_hi * DMODEL + col) = o1;
    }
}

// ===========================================================================
// Launch
// ===========================================================================
extern "C" void kernel_launch(void* const* d_in, const int* in_sizes, int n_in,
                              void* d_out, int out_size) {
    const float* x     = (const float*)d_in[0];
    const float* w_in  = (const float*)d_in[2];
    const float* b_in  = (const float*)d_in[3];
    const float* w_out = (const float*)d_in[4];
    const float* b_out = (const float*)d_in[5];
    float* out = (float*)d_out;

    float* qkv;   cudaGetSymbolAddress((void**)&qkv,  g_qkv);
    float* attn;  cudaGetSymbolAddress((void**)&attn, g_attn);

    cudaFuncSetAttribute(attn_mma_kernel,
                         cudaFuncAttributeMaxDynamicSharedMemorySize,
                         ATT_SMEM_FLOATS * (int)sizeof(float));
    cudaFuncSetAttribute(mma_gemm_kernel,
                         cudaFuncAttributeMaxDynamicSharedMemorySize,
                         GEMM_SMEM);

    // 1. RoPE tables
    rope_table_kernel<<<(SEQ * 64 + 255) / 256, 256>>>();

    // 2. QKV projection (fp16 mma, fp32 accum)
    mma_gemm_kernel<<<dim3(D3 / 128, (BATCH * SEQ) / 128), 256, GEMM_SMEM>>>(
        x, w_in, b_in, qkv, D3);

    // 3. Flash attention (tf32, proven)
    attn_mma_kernel<<<dim3(SEQ / 128, NHEAD, BATCH), 256,
                      ATT_SMEM_FLOATS * sizeof(float)>>>(qkv, attn);

    // 4. Output projection (fp16 mma, fp32 accum)
    mma_gemm_kernel<<<dim3(DMODEL / 128, (BATCH * SEQ) / 128), 256, GEMM_SMEM>>>(
        attn, w_out, b_out, out, DMODEL);
}